// round 7
// baseline (speedup 1.0000x reference)
#include <cuda_runtime.h>
#include <cuda_bf16.h>

#define B_   16
#define C_   192
#define TX_  512
#define TY_  2048
#define SEG_ 32
#define K2_  384          // 2*C
#define NEG_INF_ (-1e9f)
#define CHK_ 16           // DP chunk rows (skew unit between warps)

// ---------------- scratch (device globals: no runtime allocation) ----------------
__device__ float g_B[B_ * K2_ * TX_];
__device__ float g_cvec[B_ * TX_];
__device__ float g_negcent[(size_t)B_ * TY_ * TX_];  // 64 MB
__device__ int   g_idx[B_ * TY_];

// ---------------- helpers ----------------
union F2 { float2 f; unsigned long long u; };

__device__ __forceinline__ unsigned long long ffma2(unsigned long long a,
                                                    unsigned long long b,
                                                    unsigned long long c) {
    unsigned long long d;
    asm("fma.rn.f32x2 %0, %1, %2, %3;" : "=l"(d) : "l"(a), "l"(b), "l"(c));
    return d;
}

// ---------------- prep: B matrix ----------------
__global__ void prep_kernel(const float* __restrict__ m_p, const float* __restrict__ logs_p) {
    int i = blockIdx.x * blockDim.x + threadIdx.x;   // over B*C*TX
    if (i >= B_ * C_ * TX_) return;
    int s = i % TX_;
    int c = (i / TX_) % C_;
    int b = i / (TX_ * C_);
    float lg = logs_p[i];
    float mp = m_p[i];
    float se = expf(-2.0f * lg);
    g_B[(b * K2_ + c) * TX_ + s]        = se;
    g_B[(b * K2_ + C_ + c) * TX_ + s]   = se * mp;
}

// ---------------- prep: per-column constant ----------------
__global__ void cvec_kernel(const float* __restrict__ m_p, const float* __restrict__ logs_p) {
    int b = blockIdx.x;
    int s = threadIdx.x;                              // 512 threads
    float acc = 0.f;
    for (int c = 0; c < C_; c++) {
        int off = (b * C_ + c) * TX_ + s;
        float lg = logs_p[off];
        float mp = m_p[off];
        float se = expf(-2.0f * lg);
        acc += -0.5f * se * mp * mp - lg;
    }
    g_cvec[b * TX_ + s] = acc;
}

// ---------------- GEMM: neg_cent = A^T B + cvec ----------------
#define BM 128
#define BN 128
#define BK 16

__global__ void __launch_bounds__(256) gemm_kernel(const float* __restrict__ z_p,
                                                   const int* __restrict__ x_lengths,
                                                   const int* __restrict__ y_lengths)
{
    const int b  = blockIdx.z;
    const int m0 = blockIdx.y * BM;
    const int n0 = blockIdx.x * BN;
    if (m0 >= y_lengths[b]) return;     // rows >= t_y never used
    if (n0 >= x_lengths[b]) return;     // cols >= t_x never influence the path

    __shared__ float As[2][BK][BM];
    __shared__ float Bs[2][BK][BN];

    const int tid   = threadIdx.x;
    const int kRow  = tid >> 4;
    const int lbase = (tid & 15) << 3;
    const int mBase = (tid >> 4) << 3;
    const int nBase = (tid & 15) << 3;

    const float* zpb = z_p + b * C_ * TY_;
    const float* Bb  = g_B + b * K2_ * TX_;

    F2 acc[8][4];
#pragma unroll
    for (int i = 0; i < 8; i++)
#pragma unroll
        for (int j = 0; j < 4; j++) { acc[i][j].f.x = 0.f; acc[i][j].f.y = 0.f; }

    float4 ra0, ra1, rb0, rb1;

    {
        int kk = kRow;
        int cA = (kk < C_) ? kk : kk - C_;
        const float* pA = zpb + cA * TY_ + m0 + lbase;
        ra0 = *(const float4*)pA;
        ra1 = *(const float4*)(pA + 4);
        if (kk < C_) {
            ra0.x = -0.5f * ra0.x * ra0.x; ra0.y = -0.5f * ra0.y * ra0.y;
            ra0.z = -0.5f * ra0.z * ra0.z; ra0.w = -0.5f * ra0.w * ra0.w;
            ra1.x = -0.5f * ra1.x * ra1.x; ra1.y = -0.5f * ra1.y * ra1.y;
            ra1.z = -0.5f * ra1.z * ra1.z; ra1.w = -0.5f * ra1.w * ra1.w;
        }
        const float* pB = Bb + kk * TX_ + n0 + lbase;
        rb0 = *(const float4*)pB;
        rb1 = *(const float4*)(pB + 4);
    }
    *(float4*)&As[0][kRow][lbase]     = ra0;
    *(float4*)&As[0][kRow][lbase + 4] = ra1;
    *(float4*)&Bs[0][kRow][lbase]     = rb0;
    *(float4*)&Bs[0][kRow][lbase + 4] = rb1;
    __syncthreads();

    const int NIT = K2_ / BK;   // 24
    for (int it = 0; it < NIT; ++it) {
        const int cur = it & 1;
        if (it + 1 < NIT) {
            int kk = (it + 1) * BK + kRow;
            int cA = (kk < C_) ? kk : kk - C_;
            const float* pA = zpb + cA * TY_ + m0 + lbase;
            ra0 = *(const float4*)pA;
            ra1 = *(const float4*)(pA + 4);
            if (kk < C_) {
                ra0.x = -0.5f * ra0.x * ra0.x; ra0.y = -0.5f * ra0.y * ra0.y;
                ra0.z = -0.5f * ra0.z * ra0.z; ra0.w = -0.5f * ra0.w * ra0.w;
                ra1.x = -0.5f * ra1.x * ra1.x; ra1.y = -0.5f * ra1.y * ra1.y;
                ra1.z = -0.5f * ra1.z * ra1.z; ra1.w = -0.5f * ra1.w * ra1.w;
            }
            const float* pB = Bb + kk * TX_ + n0 + lbase;
            rb0 = *(const float4*)pB;
            rb1 = *(const float4*)(pB + 4);
        }
#pragma unroll
        for (int k = 0; k < BK; k++) {
            float4 a0 = *(const float4*)&As[cur][k][mBase];
            float4 a1 = *(const float4*)&As[cur][k][mBase + 4];
            float4 b0 = *(const float4*)&Bs[cur][k][nBase];
            float4 b1 = *(const float4*)&Bs[cur][k][nBase + 4];
            F2 bb[4];
            bb[0].f = make_float2(b0.x, b0.y);
            bb[1].f = make_float2(b0.z, b0.w);
            bb[2].f = make_float2(b1.x, b1.y);
            bb[3].f = make_float2(b1.z, b1.w);
            float a[8] = {a0.x, a0.y, a0.z, a0.w, a1.x, a1.y, a1.z, a1.w};
#pragma unroll
            for (int i = 0; i < 8; i++) {
                F2 aa; aa.f = make_float2(a[i], a[i]);
#pragma unroll
                for (int j = 0; j < 4; j++)
                    acc[i][j].u = ffma2(aa.u, bb[j].u, acc[i][j].u);
            }
        }
        if (it + 1 < NIT) {
            const int nxt = cur ^ 1;
            *(float4*)&As[nxt][kRow][lbase]     = ra0;
            *(float4*)&As[nxt][kRow][lbase + 4] = ra1;
            *(float4*)&Bs[nxt][kRow][lbase]     = rb0;
            *(float4*)&Bs[nxt][kRow][lbase + 4] = rb1;
        }
        __syncthreads();
    }

    // epilogue: add per-column constant and store
    float4 cv0 = *(const float4*)(g_cvec + b * TX_ + n0 + nBase);
    float4 cv1 = *(const float4*)(g_cvec + b * TX_ + n0 + nBase + 4);
    float* outbase = g_negcent + ((size_t)b * TY_ + m0 + mBase) * TX_ + n0 + nBase;
#pragma unroll
    for (int i = 0; i < 8; i++) {
        float4 o0, o1;
        o0.x = acc[i][0].f.x + cv0.x; o0.y = acc[i][0].f.y + cv0.y;
        o0.z = acc[i][1].f.x + cv0.z; o0.w = acc[i][1].f.y + cv0.w;
        o1.x = acc[i][2].f.x + cv1.x; o1.y = acc[i][2].f.y + cv1.y;
        o1.z = acc[i][3].f.x + cv1.z; o1.w = acc[i][3].f.y + cv1.w;
        float* op = outbase + (size_t)i * TX_;
        *(float4*)op       = o0;
        *(float4*)(op + 4) = o1;
    }
}

// ---------------- MAS DP: 4-warp chunk-skewed wavefront ----------------
// Warp w owns cols [128w, 128w+128), lane owns 4 cols. Warp w runs >=1 chunk (16 rows)
// behind warp w-1; boundary values (col 128w-1, per row) flow via smem column bnd[w-1][t],
// ordering enforced by a per-chunk flag + __threadfence_block (no per-row barriers).
// dirs[t][w*4+q] bit L = dirn for col 128w + 4L + q.
__global__ void __launch_bounds__(128) dp_kernel(const int* __restrict__ x_lengths,
                                                 const int* __restrict__ y_lengths)
{
    extern __shared__ char sdyn[];
    unsigned int* dirs = (unsigned int*)sdyn;                         // [TY_][16]
    float* bnd = (float*)(sdyn + (size_t)TY_ * 16 * 4);               // [4][TY_+1]
    int* flags = (int*)(bnd + 4 * (TY_ + 1));                         // [4]

    const int b    = blockIdx.x;
    const int tid  = threadIdx.x;
    const int lane = tid & 31;
    const int w    = tid >> 5;
    const int t_x  = min(x_lengths[b], TX_);
    const int t_y  = min(y_lengths[b], TY_);
    const int nch  = (t_y + CHK_ - 1) / CHK_;

    if (tid < 4) flags[tid] = 0;
    if (lane == 0) bnd[w * (TY_ + 1)] = NEG_INF_;
    __syncthreads();

    const float4* fsrc = (const float4*)(g_negcent + (size_t)b * TY_ * TX_);  // [t][128] float4; lane-col float4 idx == tid

    float v0 = NEG_INF_, v1 = NEG_INF_, v2 = NEG_INF_, v3 = NEG_INF_;
    if (tid == 0) v0 = 0.0f;

    float4 ring[CHK_];
#pragma unroll
    for (int r = 0; r < CHK_; r++) ring[r] = fsrc[r * 128 + tid];

    const float* bndr = bnd + (w > 0 ? (w - 1) * (TY_ + 1) : 0);
    float* bndw = bnd + w * (TY_ + 1);

    for (int k = 0; k < nch; k++) {
        if (w > 0) {
            while (((volatile int*)flags)[w - 1] < k + 1) { }
            __threadfence_block();
        }
#pragma unroll
        for (int r = 0; r < CHK_; r++) {
            const int t = k * CHK_ + r;
            float4 cur = ring[r];
            int tpf = t + CHK_; tpf = (tpf < TY_) ? tpf : (TY_ - 1);   // clamped prefetch
            ring[r] = fsrc[tpf * 128 + tid];

            float sh = __shfl_up_sync(0xffffffffu, v3, 1);
            float lb = NEG_INF_;
            if (w > 0 && lane == 0) lb = bndr[t];
            float left0 = (lane == 0) ? lb : sh;

            bool d0 = left0 > v0;
            bool d1 = v0 > v1;
            bool d2 = v1 > v2;
            bool d3 = v2 > v3;
            float n0 = cur.x + fmaxf(left0, v0);
            float n1 = cur.y + fmaxf(v0, v1);
            float n2 = cur.z + fmaxf(v1, v2);
            float n3 = cur.w + fmaxf(v2, v3);
            v0 = n0; v1 = n1; v2 = n2; v3 = n3;

            unsigned b0 = __ballot_sync(0xffffffffu, d0);
            unsigned b1 = __ballot_sync(0xffffffffu, d1);
            unsigned b2 = __ballot_sync(0xffffffffu, d2);
            unsigned b3 = __ballot_sync(0xffffffffu, d3);

            if (lane == 31) bndw[t + 1] = v3;
            if (lane == 0) *(uint4*)&dirs[t * 16 + w * 4] = make_uint4(b0, b1, b2, b3);
        }
        __threadfence_block();
        if (lane == 0) ((volatile int*)flags)[w] = k + 1;
    }
    __syncthreads();

    // rows >= t_y: no path
    for (int t = t_y + tid; t < TY_; t += 128) g_idx[b * TY_ + t] = -1;

    // backtrack (single lane, chain through smem)
    if (tid == 0) {
        int idx = t_x - 1;
        for (int j = t_y - 1; j >= 0; j--) {
            g_idx[b * TY_ + j] = idx;
            int ww = idx >> 7, c = idx & 127;
            unsigned word = dirs[j * 16 + ww * 4 + (c & 3)];
            idx -= (int)((word >> (c >> 2)) & 1u);
        }
    }
}

// ---------------- attn output (one-hot rows) ----------------
__global__ void attn_kernel(float* __restrict__ out_attn) {
    const int rowid = blockIdx.x;           // b*2048 + t
    const int idx = g_idx[rowid];
    const int s0 = threadIdx.x * 4;         // 128 threads * 4 = 512
    float4 val = make_float4(0.f, 0.f, 0.f, 0.f);
    if (idx >= s0 && idx < s0 + 4) {
        if (idx == s0)          val.x = 1.f;
        else if (idx == s0 + 1) val.y = 1.f;
        else if (idx == s0 + 2) val.z = 1.f;
        else                    val.w = 1.f;
    }
    *(float4*)(out_attn + (size_t)rowid * TX_ + s0) = val;
}

// ---------------- gathered m_p / logs_p ----------------
__global__ void gather_kernel(const float* __restrict__ m_p, const float* __restrict__ logs_p,
                              float* __restrict__ out_m, float* __restrict__ out_l)
{
    int i = blockIdx.x * blockDim.x + threadIdx.x;  // over B*C*TY
    if (i >= B_ * C_ * TY_) return;
    int t = i % TY_;
    int c = (i / TY_) % C_;
    int b = i / (TY_ * C_);
    int idx = g_idx[b * TY_ + t];
    float vm = 0.f, vl = 0.f;
    if (idx >= 0) {
        int off = (b * C_ + c) * TX_ + idx;
        vm = m_p[off];
        vl = logs_p[off];
    }
    out_m[i] = vm;
    out_l[i] = vl;
}

// ---------------- random segment slice ----------------
__global__ void zslice_kernel(const float* __restrict__ z, const int* __restrict__ y_lengths,
                              const float* __restrict__ rand_u,
                              float* __restrict__ out_z, float* __restrict__ out_ids)
{
    int i = blockIdx.x * blockDim.x + threadIdx.x;  // over B*C*SEG
    if (i >= B_ * C_ * SEG_) return;
    int k = i % SEG_;
    int c = (i / SEG_) % C_;
    int b = i / (SEG_ * C_);
    int safe  = min(y_lengths[b], TY_);
    int idmax = max(safe - SEG_, 0);
    int ids   = (int)(rand_u[b] * ((float)idmax + 1e-8f));
    float vv = z[(b * C_ + c) * TY_ + ids + k];
    out_z[i] = (k < safe - ids) ? vv : 0.f;
    if (i < B_) {
        int sb = min(y_lengths[i], TY_);
        int im = max(sb - SEG_, 0);
        out_ids[i] = (float)((int)(rand_u[i] * ((float)im + 1e-8f)));
    }
}

// ---------------- launcher ----------------
extern "C" void kernel_launch(void* const* d_in, const int* in_sizes, int n_in,
                              void* d_out, int out_size)
{
    const float* z         = (const float*)d_in[0];
    const float* z_p       = (const float*)d_in[1];
    const float* m_p       = (const float*)d_in[2];
    const float* logs_p    = (const float*)d_in[3];
    const int*   x_lengths = (const int*)d_in[4];
    const int*   y_lengths = (const int*)d_in[5];
    const float* rand_u    = (const float*)d_in[6];

    float* out      = (float*)d_out;
    float* out_z    = out;                   // 16*192*32      = 98304
    float* out_ids  = out + 98304;           // 16
    float* out_attn = out + 98320;           // 16*2048*512    = 16777216
    float* out_m    = out + 16875536;        // 16*192*2048    = 6291456
    float* out_l    = out + 23166992;        // 16*192*2048    = 6291456
    (void)in_sizes; (void)n_in; (void)out_size;

    prep_kernel<<<(B_ * C_ * TX_ + 255) / 256, 256>>>(m_p, logs_p);
    cvec_kernel<<<B_, TX_>>>(m_p, logs_p);

    dim3 gg(TX_ / BN, TY_ / BM, B_);
    gemm_kernel<<<gg, 256>>>(z_p, x_lengths, y_lengths);

    const int dp_smem = TY_ * 16 * 4 + 4 * (TY_ + 1) * 4 + 4 * 4;   // dirs + bnd + flags
    cudaFuncSetAttribute(dp_kernel, cudaFuncAttributeMaxDynamicSharedMemorySize, dp_smem);
    dp_kernel<<<B_, 128, dp_smem>>>(x_lengths, y_lengths);

    attn_kernel<<<B_ * TY_, TX_ / 4>>>(out_attn);
    gather_kernel<<<(B_ * C_ * TY_ + 255) / 256, 256>>>(m_p, logs_p, out_m, out_l);
    zslice_kernel<<<(B_ * C_ * SEG_ + 255) / 256, 256>>>(z, y_lengths, rand_u, out_z, out_ids);
}

// round 8
// speedup vs baseline: 1.4832x; 1.4832x over previous
#include <cuda_runtime.h>
#include <cuda_bf16.h>
#include <cstdint>

#define B_   16
#define C_   192
#define TX_  512
#define TY_  2048
#define SEG_ 32
#define K2_  384          // 2*C
#define NEG_INF_ (-1e9f)
#define CH_  16           // DP chunk rows staged in smem per phase

// ---------------- scratch (device globals: no runtime allocation) ----------------
__device__ float g_B[B_ * K2_ * TX_];
__device__ float g_cvec[B_ * TX_];
__device__ float g_negcent[(size_t)B_ * TY_ * TX_];  // 64 MB
__device__ int   g_idx[B_ * TY_];

// ---------------- helpers ----------------
union F2 { float2 f; unsigned long long u; };

__device__ __forceinline__ unsigned long long ffma2(unsigned long long a,
                                                    unsigned long long b,
                                                    unsigned long long c) {
    unsigned long long d;
    asm("fma.rn.f32x2 %0, %1, %2, %3;" : "=l"(d) : "l"(a), "l"(b), "l"(c));
    return d;
}

#define CP_ASYNC16(smem_u32, gptr) \
    asm volatile("cp.async.cg.shared.global [%0], [%1], 16;" :: "r"(smem_u32), "l"(gptr) : "memory")
#define CP_COMMIT() asm volatile("cp.async.commit_group;" ::: "memory")
#define CP_WAIT0()  asm volatile("cp.async.wait_group 0;" ::: "memory")

// ---------------- prep: B matrix ----------------
__global__ void prep_kernel(const float* __restrict__ m_p, const float* __restrict__ logs_p) {
    int i = blockIdx.x * blockDim.x + threadIdx.x;   // over B*C*TX
    if (i >= B_ * C_ * TX_) return;
    int s = i % TX_;
    int c = (i / TX_) % C_;
    int b = i / (TX_ * C_);
    float lg = logs_p[i];
    float mp = m_p[i];
    float se = expf(-2.0f * lg);
    g_B[(b * K2_ + c) * TX_ + s]        = se;
    g_B[(b * K2_ + C_ + c) * TX_ + s]   = se * mp;
}

// ---------------- prep: per-column constant ----------------
__global__ void cvec_kernel(const float* __restrict__ m_p, const float* __restrict__ logs_p) {
    int b = blockIdx.x;
    int s = threadIdx.x;                              // 512 threads
    float acc = 0.f;
    for (int c = 0; c < C_; c++) {
        int off = (b * C_ + c) * TX_ + s;
        float lg = logs_p[off];
        float mp = m_p[off];
        float se = expf(-2.0f * lg);
        acc += -0.5f * se * mp * mp - lg;
    }
    g_cvec[b * TX_ + s] = acc;
}

// ---------------- GEMM: neg_cent = A^T B + cvec ----------------
#define BM 128
#define BN 128
#define BK 16

__global__ void __launch_bounds__(256) gemm_kernel(const float* __restrict__ z_p,
                                                   const int* __restrict__ x_lengths,
                                                   const int* __restrict__ y_lengths)
{
    const int b  = blockIdx.z;
    const int m0 = blockIdx.y * BM;
    const int n0 = blockIdx.x * BN;
    if (m0 >= y_lengths[b]) return;     // rows >= t_y never used
    if (n0 >= x_lengths[b]) return;     // cols >= t_x never influence the path

    __shared__ float As[2][BK][BM];
    __shared__ float Bs[2][BK][BN];

    const int tid   = threadIdx.x;
    const int kRow  = tid >> 4;
    const int lbase = (tid & 15) << 3;
    const int mBase = (tid >> 4) << 3;
    const int nBase = (tid & 15) << 3;

    const float* zpb = z_p + b * C_ * TY_;
    const float* Bb  = g_B + b * K2_ * TX_;

    F2 acc[8][4];
#pragma unroll
    for (int i = 0; i < 8; i++)
#pragma unroll
        for (int j = 0; j < 4; j++) { acc[i][j].f.x = 0.f; acc[i][j].f.y = 0.f; }

    float4 ra0, ra1, rb0, rb1;

    {
        int kk = kRow;
        int cA = (kk < C_) ? kk : kk - C_;
        const float* pA = zpb + cA * TY_ + m0 + lbase;
        ra0 = *(const float4*)pA;
        ra1 = *(const float4*)(pA + 4);
        if (kk < C_) {
            ra0.x = -0.5f * ra0.x * ra0.x; ra0.y = -0.5f * ra0.y * ra0.y;
            ra0.z = -0.5f * ra0.z * ra0.z; ra0.w = -0.5f * ra0.w * ra0.w;
            ra1.x = -0.5f * ra1.x * ra1.x; ra1.y = -0.5f * ra1.y * ra1.y;
            ra1.z = -0.5f * ra1.z * ra1.z; ra1.w = -0.5f * ra1.w * ra1.w;
        }
        const float* pB = Bb + kk * TX_ + n0 + lbase;
        rb0 = *(const float4*)pB;
        rb1 = *(const float4*)(pB + 4);
    }
    *(float4*)&As[0][kRow][lbase]     = ra0;
    *(float4*)&As[0][kRow][lbase + 4] = ra1;
    *(float4*)&Bs[0][kRow][lbase]     = rb0;
    *(float4*)&Bs[0][kRow][lbase + 4] = rb1;
    __syncthreads();

    const int NIT = K2_ / BK;   // 24
    for (int it = 0; it < NIT; ++it) {
        const int cur = it & 1;
        if (it + 1 < NIT) {
            int kk = (it + 1) * BK + kRow;
            int cA = (kk < C_) ? kk : kk - C_;
            const float* pA = zpb + cA * TY_ + m0 + lbase;
            ra0 = *(const float4*)pA;
            ra1 = *(const float4*)(pA + 4);
            if (kk < C_) {
                ra0.x = -0.5f * ra0.x * ra0.x; ra0.y = -0.5f * ra0.y * ra0.y;
                ra0.z = -0.5f * ra0.z * ra0.z; ra0.w = -0.5f * ra0.w * ra0.w;
                ra1.x = -0.5f * ra1.x * ra1.x; ra1.y = -0.5f * ra1.y * ra1.y;
                ra1.z = -0.5f * ra1.z * ra1.z; ra1.w = -0.5f * ra1.w * ra1.w;
            }
            const float* pB = Bb + kk * TX_ + n0 + lbase;
            rb0 = *(const float4*)pB;
            rb1 = *(const float4*)(pB + 4);
        }
#pragma unroll
        for (int k = 0; k < BK; k++) {
            float4 a0 = *(const float4*)&As[cur][k][mBase];
            float4 a1 = *(const float4*)&As[cur][k][mBase + 4];
            float4 b0 = *(const float4*)&Bs[cur][k][nBase];
            float4 b1 = *(const float4*)&Bs[cur][k][nBase + 4];
            F2 bb[4];
            bb[0].f = make_float2(b0.x, b0.y);
            bb[1].f = make_float2(b0.z, b0.w);
            bb[2].f = make_float2(b1.x, b1.y);
            bb[3].f = make_float2(b1.z, b1.w);
            float a[8] = {a0.x, a0.y, a0.z, a0.w, a1.x, a1.y, a1.z, a1.w};
#pragma unroll
            for (int i = 0; i < 8; i++) {
                F2 aa; aa.f = make_float2(a[i], a[i]);
#pragma unroll
                for (int j = 0; j < 4; j++)
                    acc[i][j].u = ffma2(aa.u, bb[j].u, acc[i][j].u);
            }
        }
        if (it + 1 < NIT) {
            const int nxt = cur ^ 1;
            *(float4*)&As[nxt][kRow][lbase]     = ra0;
            *(float4*)&As[nxt][kRow][lbase + 4] = ra1;
            *(float4*)&Bs[nxt][kRow][lbase]     = rb0;
            *(float4*)&Bs[nxt][kRow][lbase + 4] = rb1;
        }
        __syncthreads();
    }

    // epilogue: add per-column constant and store
    float4 cv0 = *(const float4*)(g_cvec + b * TX_ + n0 + nBase);
    float4 cv1 = *(const float4*)(g_cvec + b * TX_ + n0 + nBase + 4);
    float* outbase = g_negcent + ((size_t)b * TY_ + m0 + mBase) * TX_ + n0 + nBase;
#pragma unroll
    for (int i = 0; i < 8; i++) {
        float4 o0, o1;
        o0.x = acc[i][0].f.x + cv0.x; o0.y = acc[i][0].f.y + cv0.y;
        o0.z = acc[i][1].f.x + cv0.z; o0.w = acc[i][1].f.y + cv0.w;
        o1.x = acc[i][2].f.x + cv1.x; o1.y = acc[i][2].f.y + cv1.y;
        o1.z = acc[i][3].f.x + cv1.z; o1.w = acc[i][3].f.y + cv1.w;
        float* op = outbase + (size_t)i * TX_;
        *(float4*)op       = o0;
        *(float4*)(op + 4) = o1;
    }
}

// ---------------- MAS DP: warp 0 computes, warps 1-3 stream rows via cp.async ----------------
// Direction bit = sign of (v[j] - v[j-1]); no predicates, no branches.
__device__ __forceinline__ void dp_row(float4 (&cur)[4], float (&v)[16],
                                       unsigned short* dirs, int t, int lane)
{
    float sh = __shfl_up_sync(0xffffffffu, v[15], 1);
    float left0 = (lane == 0) ? NEG_INF_ : sh;

    float r[16];
    r[0]=cur[0].x;  r[1]=cur[0].y;  r[2]=cur[0].z;  r[3]=cur[0].w;
    r[4]=cur[1].x;  r[5]=cur[1].y;  r[6]=cur[1].z;  r[7]=cur[1].w;
    r[8]=cur[2].x;  r[9]=cur[2].y;  r[10]=cur[2].z; r[11]=cur[2].w;
    r[12]=cur[3].x; r[13]=cur[3].y; r[14]=cur[3].z; r[15]=cur[3].w;

    unsigned bits = 0u;
#pragma unroll
    for (int j = 15; j >= 1; j--) {
        float left = v[j - 1];
        float d = v[j] - left;                     // sign=1  <=>  left > v[j]  (strict; equal -> +0)
        bits |= (__float_as_uint(d) >> (31 - j)) & (1u << j);
        v[j] = r[j] + fmaxf(left, v[j]);           // no clamp: unreachable cells drift, path cells unaffected
    }
    float d0 = v[0] - left0;
    bits |= (__float_as_uint(d0) >> 31);
    v[0] = r[0] + fmaxf(left0, v[0]);

    dirs[t * 32 + lane] = (unsigned short)bits;
}

__global__ void __launch_bounds__(128) dp_kernel(const int* __restrict__ x_lengths,
                                                 const int* __restrict__ y_lengths)
{
    extern __shared__ char sdyn[];
    unsigned short* dirs = (unsigned short*)sdyn;                      // [TY_][32]
    float4* rowbuf = (float4*)(sdyn + (size_t)TY_ * 32 * 2);           // [2][CH_][128]

    const int b    = blockIdx.x;
    const int tid  = threadIdx.x;
    const int lane = tid & 31;
    const int w    = tid >> 5;
    const int t_x  = min(x_lengths[b], TX_);
    const int t_y  = min(y_lengths[b], TY_);
    const int nch  = (t_y + CH_ - 1) / CH_;                            // <= 128

    const float4* src = (const float4*)(g_negcent + (size_t)b * TY_ * TX_);  // 128 float4/row
    const uint32_t rb_u32 = (uint32_t)__cvta_generic_to_shared(rowbuf);

    // ---- loader prologue: chunk 0 via cp.async (no LDG->STS serialization) ----
    if (w > 0) {
        const int lid = tid - 32;                                      // 0..95
        for (int p = lid; p < CH_ * 128; p += 96)
            CP_ASYNC16(rb_u32 + p * 16, src + (size_t)(p >> 7) * 128 + (p & 127));
        CP_COMMIT();
        CP_WAIT0();
    }

    float v[16];
#pragma unroll
    for (int j = 0; j < 16; j++) v[j] = NEG_INF_;
    if (tid == 0) v[0] = 0.0f;
    __syncthreads();

    for (int k = 0; k < nch; k++) {
        if (w > 0) {
            // loaders: stream chunk k+1 (fire-and-forget; arrival overlapped with compute of k)
            if (k + 1 < nch) {
                const int lid = tid - 32;
                const int t0 = (k + 1) * CH_;
                const uint32_t dstb = rb_u32 + (uint32_t)(((k + 1) & 1) * CH_ * 128 * 16);
                for (int p = lid; p < CH_ * 128; p += 96)
                    CP_ASYNC16(dstb + p * 16, src + (size_t)(t0 + (p >> 7)) * 128 + (p & 127));
                CP_COMMIT();
                CP_WAIT0();
            }
        } else {
            // compute warp: 16 rows from smem, one-row LDS prefetch
            const float4* bufb = rowbuf + (k & 1) * CH_ * 128 + lane * 4;
            const int tb = k * CH_;
            float4 cur[4], nxt[4];
            cur[0] = bufb[0]; cur[1] = bufb[1]; cur[2] = bufb[2]; cur[3] = bufb[3];
#pragma unroll
            for (int r = 0; r < CH_ - 1; r++) {
                const float4* pn = bufb + (r + 1) * 128;
                nxt[0] = pn[0]; nxt[1] = pn[1]; nxt[2] = pn[2]; nxt[3] = pn[3];
                dp_row(cur, v, dirs, tb + r, lane);
                cur[0] = nxt[0]; cur[1] = nxt[1]; cur[2] = nxt[2]; cur[3] = nxt[3];
            }
            dp_row(cur, v, dirs, tb + CH_ - 1, lane);
        }
        __syncthreads();
    }

    // rows >= t_y: no path
    for (int t = t_y + tid; t < TY_; t += 128) g_idx[b * TY_ + t] = -1;

    // backtrack (single lane, chain through smem)
    if (tid == 0) {
        int idx = t_x - 1;
        for (int j = t_y - 1; j >= 0; j--) {
            g_idx[b * TY_ + j] = idx;
            unsigned int word = dirs[j * 32 + (idx >> 4)];
            idx -= (int)((word >> (idx & 15)) & 1u);
        }
    }
}

// ---------------- attn output (one-hot rows) ----------------
__global__ void attn_kernel(float* __restrict__ out_attn) {
    const int rowid = blockIdx.x;           // b*2048 + t
    const int idx = g_idx[rowid];
    const int s0 = threadIdx.x * 4;         // 128 threads * 4 = 512
    float4 val = make_float4(0.f, 0.f, 0.f, 0.f);
    if (idx >= s0 && idx < s0 + 4) {
        if (idx == s0)          val.x = 1.f;
        else if (idx == s0 + 1) val.y = 1.f;
        else if (idx == s0 + 2) val.z = 1.f;
        else                    val.w = 1.f;
    }
    *(float4*)(out_attn + (size_t)rowid * TX_ + s0) = val;
}

// ---------------- gathered m_p / logs_p ----------------
__global__ void gather_kernel(const float* __restrict__ m_p, const float* __restrict__ logs_p,
                              float* __restrict__ out_m, float* __restrict__ out_l)
{
    int i = blockIdx.x * blockDim.x + threadIdx.x;  // over B*C*TY
    if (i >= B_ * C_ * TY_) return;
    int t = i % TY_;
    int c = (i / TY_) % C_;
    int b = i / (TY_ * C_);
    int idx = g_idx[b * TY_ + t];
    float vm = 0.f, vl = 0.f;
    if (idx >= 0) {
        int off = (b * C_ + c) * TX_ + idx;
        vm = m_p[off];
        vl = logs_p[off];
    }
    out_m[i] = vm;
    out_l[i] = vl;
}

// ---------------- random segment slice ----------------
__global__ void zslice_kernel(const float* __restrict__ z, const int* __restrict__ y_lengths,
                              const float* __restrict__ rand_u,
                              float* __restrict__ out_z, float* __restrict__ out_ids)
{
    int i = blockIdx.x * blockDim.x + threadIdx.x;  // over B*C*SEG
    if (i >= B_ * C_ * SEG_) return;
    int k = i % SEG_;
    int c = (i / SEG_) % C_;
    int b = i / (SEG_ * C_);
    int safe  = min(y_lengths[b], TY_);
    int idmax = max(safe - SEG_, 0);
    int ids   = (int)(rand_u[b] * ((float)idmax + 1e-8f));
    float vv = z[(b * C_ + c) * TY_ + ids + k];
    out_z[i] = (k < safe - ids) ? vv : 0.f;
    if (i < B_) {
        int sb = min(y_lengths[i], TY_);
        int im = max(sb - SEG_, 0);
        out_ids[i] = (float)((int)(rand_u[i] * ((float)im + 1e-8f)));
    }
}

// ---------------- launcher ----------------
extern "C" void kernel_launch(void* const* d_in, const int* in_sizes, int n_in,
                              void* d_out, int out_size)
{
    const float* z         = (const float*)d_in[0];
    const float* z_p       = (const float*)d_in[1];
    const float* m_p       = (const float*)d_in[2];
    const float* logs_p    = (const float*)d_in[3];
    const int*   x_lengths = (const int*)d_in[4];
    const int*   y_lengths = (const int*)d_in[5];
    const float* rand_u    = (const float*)d_in[6];

    float* out      = (float*)d_out;
    float* out_z    = out;                   // 16*192*32      = 98304
    float* out_ids  = out + 98304;           // 16
    float* out_attn = out + 98320;           // 16*2048*512    = 16777216
    float* out_m    = out + 16875536;        // 16*192*2048    = 6291456
    float* out_l    = out + 23166992;        // 16*192*2048    = 6291456
    (void)in_sizes; (void)n_in; (void)out_size;

    prep_kernel<<<(B_ * C_ * TX_ + 255) / 256, 256>>>(m_p, logs_p);
    cvec_kernel<<<B_, TX_>>>(m_p, logs_p);

    dim3 gg(TX_ / BN, TY_ / BM, B_);
    gemm_kernel<<<gg, 256>>>(z_p, x_lengths, y_lengths);

    const int dp_smem = TY_ * 32 * 2 + 2 * CH_ * 128 * 16;   // dirs(128KB) + rowbuf(64KB)
    cudaFuncSetAttribute(dp_kernel, cudaFuncAttributeMaxDynamicSharedMemorySize, dp_smem);
    dp_kernel<<<B_, 128, dp_smem>>>(x_lengths, y_lengths);

    attn_kernel<<<B_ * TY_, TX_ / 4>>>(out_attn);
    gather_kernel<<<(B_ * C_ * TY_ + 255) / 256, 256>>>(m_p, logs_p, out_m, out_l);
    zslice_kernel<<<(B_ * C_ * SEG_ + 255) / 256, 256>>>(z, y_lengths, rand_u, out_z, out_ids);
}

// round 9
// speedup vs baseline: 1.7907x; 1.2074x over previous
#include <cuda_runtime.h>
#include <cuda_bf16.h>
#include <cstdint>

#define B_   16
#define C_   192
#define TX_  512
#define TY_  2048
#define SEG_ 32
#define K2_  384          // 2*C
#define NEG_INF_ (-1e9f)
#define CH_  16           // DP chunk rows staged in smem per phase
#define NLOAD_ 224        // dp loader lanes (7 warps)

// ---------------- scratch (device globals: no runtime allocation) ----------------
__device__ float g_B[B_ * K2_ * TX_];
__device__ float g_cvec[B_ * TX_];
__device__ float g_negcent[(size_t)B_ * TY_ * TX_];  // 64 MB
__device__ int   g_idx[B_ * TY_];
__device__ int   g_cnt[B_ * 16];                     // per (b, mblk) completed n-tiles (target 4)

// ---------------- helpers ----------------
union F2 { float2 f; unsigned long long u; };

__device__ __forceinline__ unsigned long long ffma2(unsigned long long a,
                                                    unsigned long long b,
                                                    unsigned long long c) {
    unsigned long long d;
    asm("fma.rn.f32x2 %0, %1, %2, %3;" : "=l"(d) : "l"(a), "l"(b), "l"(c));
    return d;
}

__device__ __forceinline__ int ld_acq(const int* p) {
    int v;
    asm volatile("ld.acquire.gpu.global.b32 %0, [%1];" : "=r"(v) : "l"(p) : "memory");
    return v;
}

#define CP_ASYNC16(smem_u32, gptr) \
    asm volatile("cp.async.cg.shared.global [%0], [%1], 16;" :: "r"(smem_u32), "l"(gptr) : "memory")
#define CP_COMMIT() asm volatile("cp.async.commit_group;" ::: "memory")
#define CP_WAIT0()  asm volatile("cp.async.wait_group 0;" ::: "memory")

// ---------------- prep: B matrix + zero flags ----------------
__global__ void prep_kernel(const float* __restrict__ m_p, const float* __restrict__ logs_p) {
    int i = blockIdx.x * blockDim.x + threadIdx.x;   // over B*C*TX
    if (i >= B_ * C_ * TX_) return;
    if (i < B_ * 16) g_cnt[i] = 0;                   // reset producer flags every replay
    int s = i % TX_;
    int c = (i / TX_) % C_;
    int b = i / (TX_ * C_);
    float lg = logs_p[i];
    float mp = m_p[i];
    float se = expf(-2.0f * lg);
    g_B[(b * K2_ + c) * TX_ + s]        = se;
    g_B[(b * K2_ + C_ + c) * TX_ + s]   = se * mp;
}

// ---------------- prep: per-column constant ----------------
__global__ void cvec_kernel(const float* __restrict__ m_p, const float* __restrict__ logs_p) {
    int b = blockIdx.x;
    int s = threadIdx.x;                              // 512 threads
    float acc = 0.f;
    for (int c = 0; c < C_; c++) {
        int off = (b * C_ + c) * TX_ + s;
        float lg = logs_p[off];
        float mp = m_p[off];
        float se = expf(-2.0f * lg);
        acc += -0.5f * se * mp * mp - lg;
    }
    g_cvec[b * TX_ + s] = acc;
}

// ---------------- fused GEMM producer + DP consumer ----------------
#define BM 128
#define BN 128
#define BK 16

// DP row update; direction bit = sign of (v[j] - v[j-1]).
__device__ __forceinline__ void dp_row(float4 (&cur)[4], float (&v)[16],
                                       unsigned short* dirs, int t, int lane)
{
    float sh = __shfl_up_sync(0xffffffffu, v[15], 1);
    float left0 = (lane == 0) ? NEG_INF_ : sh;

    float r[16];
    r[0]=cur[0].x;  r[1]=cur[0].y;  r[2]=cur[0].z;  r[3]=cur[0].w;
    r[4]=cur[1].x;  r[5]=cur[1].y;  r[6]=cur[1].z;  r[7]=cur[1].w;
    r[8]=cur[2].x;  r[9]=cur[2].y;  r[10]=cur[2].z; r[11]=cur[2].w;
    r[12]=cur[3].x; r[13]=cur[3].y; r[14]=cur[3].z; r[15]=cur[3].w;

    unsigned bits = 0u;
#pragma unroll
    for (int j = 15; j >= 1; j--) {
        float left = v[j - 1];
        float d = v[j] - left;                     // sign=1 <=> left > v[j]
        bits |= (__float_as_uint(d) >> (31 - j)) & (1u << j);
        v[j] = r[j] + fmaxf(left, v[j]);
    }
    float d0 = v[0] - left0;
    bits |= (__float_as_uint(d0) >> 31);
    v[0] = r[0] + fmaxf(left0, v[0]);

    dirs[t * 32 + lane] = (unsigned short)bits;
}

// dynamic smem: dp CTA -> dirs(128KB) + rowbuf(64KB); gemm CTA -> As/Bs(32KB)
#define FUSED_SMEM (TY_ * 32 * 2 + 2 * CH_ * 128 * 16)

__global__ void __launch_bounds__(256) fused_kernel(const float* __restrict__ z_p,
                                                    const int* __restrict__ x_lengths,
                                                    const int* __restrict__ y_lengths)
{
    extern __shared__ char sdyn[];
    const int tid = threadIdx.x;

    if (blockIdx.x < B_) {
        // ================= DP consumer CTA (batch b) =================
        unsigned short* dirs = (unsigned short*)sdyn;                      // [TY_][32]
        float4* rowbuf = (float4*)(sdyn + (size_t)TY_ * 32 * 2);           // [2][CH_][128]

        const int b    = blockIdx.x;
        const int lane = tid & 31;
        const int w    = tid >> 5;                                         // 0..7
        const int t_x  = min(x_lengths[b], TX_);
        const int t_y  = min(y_lengths[b], TY_);
        const int nch  = (t_y + CH_ - 1) / CH_;                            // <= 128

        const float4* src = (const float4*)(g_negcent + (size_t)b * TY_ * TX_);
        const uint32_t rb_u32 = (uint32_t)__cvta_generic_to_shared(rowbuf);
        const int* cntb = g_cnt + b * 16;

        // ---- loader prologue: wait band 0, stream chunk 0 ----
        if (w > 0) {
            if (lane == 0) while (ld_acq(&cntb[0]) < 4) { }
            __syncwarp();
            const int lid = tid - 32;                                      // 0..223
            for (int p = lid; p < CH_ * 128; p += NLOAD_)
                CP_ASYNC16(rb_u32 + p * 16, src + (size_t)(p >> 7) * 128 + (p & 127));
            CP_COMMIT();
            CP_WAIT0();
        }

        float v[16];
#pragma unroll
        for (int j = 0; j < 16; j++) v[j] = NEG_INF_;
        if (tid == 0) v[0] = 0.0f;
        __syncthreads();

        for (int k = 0; k < nch; k++) {
            if (w > 0) {
                if (k + 1 < nch) {
                    const int c = k + 1;
                    if ((c & 7) == 0) {                                    // new 128-row band
                        if (lane == 0) while (ld_acq(&cntb[c >> 3]) < 4) { }
                        __syncwarp();
                    }
                    const int lid = tid - 32;
                    const int t0 = c * CH_;
                    const uint32_t dstb = rb_u32 + (uint32_t)((c & 1) * CH_ * 128 * 16);
                    for (int p = lid; p < CH_ * 128; p += NLOAD_)
                        CP_ASYNC16(dstb + p * 16, src + (size_t)(t0 + (p >> 7)) * 128 + (p & 127));
                    CP_COMMIT();
                    CP_WAIT0();
                }
            } else {
                const float4* bufb = rowbuf + (k & 1) * CH_ * 128 + lane * 4;
                const int tb = k * CH_;
                float4 cur[4], nxt[4];
                cur[0] = bufb[0]; cur[1] = bufb[1]; cur[2] = bufb[2]; cur[3] = bufb[3];
#pragma unroll
                for (int r = 0; r < CH_ - 1; r++) {
                    const float4* pn = bufb + (r + 1) * 128;
                    nxt[0] = pn[0]; nxt[1] = pn[1]; nxt[2] = pn[2]; nxt[3] = pn[3];
                    dp_row(cur, v, dirs, tb + r, lane);
                    cur[0] = nxt[0]; cur[1] = nxt[1]; cur[2] = nxt[2]; cur[3] = nxt[3];
                }
                dp_row(cur, v, dirs, tb + CH_ - 1, lane);
            }
            __syncthreads();
        }

        // rows >= t_y: no path
        for (int t = t_y + tid; t < TY_; t += 256) g_idx[b * TY_ + t] = -1;

        // backtrack (single lane)
        if (tid == 0) {
            int idx = t_x - 1;
            for (int j = t_y - 1; j >= 0; j--) {
                g_idx[b * TY_ + j] = idx;
                unsigned int word = dirs[j * 32 + (idx >> 4)];
                idx -= (int)((word >> (idx & 15)) & 1u);
            }
        }
        return;
    }

    // ================= GEMM producer CTA =================
    {
        const int r   = blockIdx.x - B_;
        const int nb  = r & 3;                   // 4 n-blocks
        const int b   = (r >> 2) & 15;           // 16 batches
        const int mblk= r >> 6;                  // 16 m-blocks (low bands first)
        const int m0  = mblk * BM;
        const int n0  = nb * BN;

        typedef float TileT[BK][BM];
        TileT* As = (TileT*)sdyn;                            // [2][BK][BM] 16KB
        TileT* Bs = (TileT*)(sdyn + 2 * BK * BM * 4);        // [2][BK][BN] 16KB

        const bool active = (m0 < y_lengths[b]) && (n0 < x_lengths[b]);

        if (active) {
            const int kRow  = tid >> 4;
            const int lbase = (tid & 15) << 3;
            const int mBase = (tid >> 4) << 3;
            const int nBase = (tid & 15) << 3;

            const float* zpb = z_p + b * C_ * TY_;
            const float* Bb  = g_B + b * K2_ * TX_;

            F2 acc[8][4];
#pragma unroll
            for (int i = 0; i < 8; i++)
#pragma unroll
                for (int j = 0; j < 4; j++) { acc[i][j].f.x = 0.f; acc[i][j].f.y = 0.f; }

            float4 ra0, ra1, rb0, rb1;
            {
                int kk = kRow;
                int cA = (kk < C_) ? kk : kk - C_;
                const float* pA = zpb + cA * TY_ + m0 + lbase;
                ra0 = *(const float4*)pA;
                ra1 = *(const float4*)(pA + 4);
                if (kk < C_) {
                    ra0.x = -0.5f * ra0.x * ra0.x; ra0.y = -0.5f * ra0.y * ra0.y;
                    ra0.z = -0.5f * ra0.z * ra0.z; ra0.w = -0.5f * ra0.w * ra0.w;
                    ra1.x = -0.5f * ra1.x * ra1.x; ra1.y = -0.5f * ra1.y * ra1.y;
                    ra1.z = -0.5f * ra1.z * ra1.z; ra1.w = -0.5f * ra1.w * ra1.w;
                }
                const float* pB = Bb + kk * TX_ + n0 + lbase;
                rb0 = *(const float4*)pB;
                rb1 = *(const float4*)(pB + 4);
            }
            *(float4*)&As[0][kRow][lbase]     = ra0;
            *(float4*)&As[0][kRow][lbase + 4] = ra1;
            *(float4*)&Bs[0][kRow][lbase]     = rb0;
            *(float4*)&Bs[0][kRow][lbase + 4] = rb1;
            __syncthreads();

            const int NIT = K2_ / BK;   // 24
            for (int it = 0; it < NIT; ++it) {
                const int cur = it & 1;
                if (it + 1 < NIT) {
                    int kk = (it + 1) * BK + kRow;
                    int cA = (kk < C_) ? kk : kk - C_;
                    const float* pA = zpb + cA * TY_ + m0 + lbase;
                    ra0 = *(const float4*)pA;
                    ra1 = *(const float4*)(pA + 4);
                    if (kk < C_) {
                        ra0.x = -0.5f * ra0.x * ra0.x; ra0.y = -0.5f * ra0.y * ra0.y;
                        ra0.z = -0.5f * ra0.z * ra0.z; ra0.w = -0.5f * ra0.w * ra0.w;
                        ra1.x = -0.5f * ra1.x * ra1.x; ra1.y = -0.5f * ra1.y * ra1.y;
                        ra1.z = -0.5f * ra1.z * ra1.z; ra1.w = -0.5f * ra1.w * ra1.w;
                    }
                    const float* pB = Bb + kk * TX_ + n0 + lbase;
                    rb0 = *(const float4*)pB;
                    rb1 = *(const float4*)(pB + 4);
                }
#pragma unroll
                for (int k = 0; k < BK; k++) {
                    float4 a0 = *(const float4*)&As[cur][k][mBase];
                    float4 a1 = *(const float4*)&As[cur][k][mBase + 4];
                    float4 b0 = *(const float4*)&Bs[cur][k][nBase];
                    float4 b1 = *(const float4*)&Bs[cur][k][nBase + 4];
                    F2 bb[4];
                    bb[0].f = make_float2(b0.x, b0.y);
                    bb[1].f = make_float2(b0.z, b0.w);
                    bb[2].f = make_float2(b1.x, b1.y);
                    bb[3].f = make_float2(b1.z, b1.w);
                    float a[8] = {a0.x, a0.y, a0.z, a0.w, a1.x, a1.y, a1.z, a1.w};
#pragma unroll
                    for (int i = 0; i < 8; i++) {
                        F2 aa; aa.f = make_float2(a[i], a[i]);
#pragma unroll
                        for (int j = 0; j < 4; j++)
                            acc[i][j].u = ffma2(aa.u, bb[j].u, acc[i][j].u);
                    }
                }
                if (it + 1 < NIT) {
                    const int nxt = cur ^ 1;
                    *(float4*)&As[nxt][kRow][lbase]     = ra0;
                    *(float4*)&As[nxt][kRow][lbase + 4] = ra1;
                    *(float4*)&Bs[nxt][kRow][lbase]     = rb0;
                    *(float4*)&Bs[nxt][kRow][lbase + 4] = rb1;
                }
                __syncthreads();
            }

            // epilogue: add per-column constant and store
            float4 cv0 = *(const float4*)(g_cvec + b * TX_ + n0 + nBase);
            float4 cv1 = *(const float4*)(g_cvec + b * TX_ + n0 + nBase + 4);
            float* outbase = g_negcent + ((size_t)b * TY_ + m0 + mBase) * TX_ + n0 + nBase;
#pragma unroll
            for (int i = 0; i < 8; i++) {
                float4 o0, o1;
                o0.x = acc[i][0].f.x + cv0.x; o0.y = acc[i][0].f.y + cv0.y;
                o0.z = acc[i][1].f.x + cv0.z; o0.w = acc[i][1].f.y + cv0.w;
                o1.x = acc[i][2].f.x + cv1.x; o1.y = acc[i][2].f.y + cv1.y;
                o1.z = acc[i][3].f.x + cv1.z; o1.w = acc[i][3].f.y + cv1.w;
                float* op = outbase + (size_t)i * TX_;
                *(float4*)op       = o0;
                *(float4*)(op + 4) = o1;
            }
            __syncthreads();
        }

        // signal band completion (also for skipped tiles)
        if (tid == 0) {
            __threadfence();
            atomicAdd(&g_cnt[b * 16 + mblk], 1);
        }
    }
}

// ---------------- attn output (one-hot rows) ----------------
__global__ void attn_kernel(float* __restrict__ out_attn) {
    const int rowid = blockIdx.x;           // b*2048 + t
    const int idx = g_idx[rowid];
    const int s0 = threadIdx.x * 4;         // 128 threads * 4 = 512
    float4 val = make_float4(0.f, 0.f, 0.f, 0.f);
    if (idx >= s0 && idx < s0 + 4) {
        if (idx == s0)          val.x = 1.f;
        else if (idx == s0 + 1) val.y = 1.f;
        else if (idx == s0 + 2) val.z = 1.f;
        else                    val.w = 1.f;
    }
    *(float4*)(out_attn + (size_t)rowid * TX_ + s0) = val;
}

// ---------------- gathered m_p / logs_p ----------------
__global__ void gather_kernel(const float* __restrict__ m_p, const float* __restrict__ logs_p,
                              float* __restrict__ out_m, float* __restrict__ out_l)
{
    int i = blockIdx.x * blockDim.x + threadIdx.x;  // over B*C*TY
    if (i >= B_ * C_ * TY_) return;
    int t = i % TY_;
    int c = (i / TY_) % C_;
    int b = i / (TY_ * C_);
    int idx = g_idx[b * TY_ + t];
    float vm = 0.f, vl = 0.f;
    if (idx >= 0) {
        int off = (b * C_ + c) * TX_ + idx;
        vm = m_p[off];
        vl = logs_p[off];
    }
    out_m[i] = vm;
    out_l[i] = vl;
}

// ---------------- random segment slice ----------------
__global__ void zslice_kernel(const float* __restrict__ z, const int* __restrict__ y_lengths,
                              const float* __restrict__ rand_u,
                              float* __restrict__ out_z, float* __restrict__ out_ids)
{
    int i = blockIdx.x * blockDim.x + threadIdx.x;  // over B*C*SEG
    if (i >= B_ * C_ * SEG_) return;
    int k = i % SEG_;
    int c = (i / SEG_) % C_;
    int b = i / (SEG_ * C_);
    int safe  = min(y_lengths[b], TY_);
    int idmax = max(safe - SEG_, 0);
    int ids   = (int)(rand_u[b] * ((float)idmax + 1e-8f));
    float vv = z[(b * C_ + c) * TY_ + ids + k];
    out_z[i] = (k < safe - ids) ? vv : 0.f;
    if (i < B_) {
        int sb = min(y_lengths[i], TY_);
        int im = max(sb - SEG_, 0);
        out_ids[i] = (float)((int)(rand_u[i] * ((float)im + 1e-8f)));
    }
}

// ---------------- launcher ----------------
extern "C" void kernel_launch(void* const* d_in, const int* in_sizes, int n_in,
                              void* d_out, int out_size)
{
    const float* z         = (const float*)d_in[0];
    const float* z_p       = (const float*)d_in[1];
    const float* m_p       = (const float*)d_in[2];
    const float* logs_p    = (const float*)d_in[3];
    const int*   x_lengths = (const int*)d_in[4];
    const int*   y_lengths = (const int*)d_in[5];
    const float* rand_u    = (const float*)d_in[6];

    float* out      = (float*)d_out;
    float* out_z    = out;                   // 16*192*32      = 98304
    float* out_ids  = out + 98304;           // 16
    float* out_attn = out + 98320;           // 16*2048*512    = 16777216
    float* out_m    = out + 16875536;        // 16*192*2048    = 6291456
    float* out_l    = out + 23166992;        // 16*192*2048    = 6291456
    (void)in_sizes; (void)n_in; (void)out_size;

    prep_kernel<<<(B_ * C_ * TX_ + 255) / 256, 256>>>(m_p, logs_p);
    cvec_kernel<<<B_, TX_>>>(m_p, logs_p);

    cudaFuncSetAttribute(fused_kernel, cudaFuncAttributeMaxDynamicSharedMemorySize, FUSED_SMEM);
    fused_kernel<<<B_ + 4 * 16 * 16, 256, FUSED_SMEM>>>(z_p, x_lengths, y_lengths);

    attn_kernel<<<B_ * TY_, TX_ / 4>>>(out_attn);
    gather_kernel<<<(B_ * C_ * TY_ + 255) / 256, 256>>>(m_p, logs_p, out_m, out_l);
    zslice_kernel<<<(B_ * C_ * SEG_ + 255) / 256, 256>>>(z, y_lengths, rand_u, out_z, out_ids);
}